// round 10
// baseline (speedup 1.0000x reference)
#include <cuda_runtime.h>
#include <math.h>

// mask [8,256,256] fp32 -> EDT (separable squared) -> normalize by global max -> sigmoid.
// 2-kernel pipeline:
//   k_row : warp-per-row; 2x LDG.128 + nibble-shfl bitmap; nearest-set-bit -> g_tmp u16.
//           Also resets barrier counter + global max (stream-ordered => graph-safe).
//   k_fuse: 64 blocks x 1024 thr (32 cols/block). Column min-plus with exact prune
//           (d2 in registers), per-block atomicMax, single 64-arrival spin barrier,
//           fused sigmoid epilogue.
constexpr int B_ = 8;
constexpr int H_ = 256;
constexpr int W_ = 256;
constexpr int NT = B_ * H_ * W_;
constexpr float THR   = 0.5f;
constexpr float INF_F = 1e10f;
constexpr int BIG = 1 << 29;
constexpr int NBLK2 = 64;          // 8 images * 8 column-tiles
constexpr int CPB2  = 32;          // columns per k_fuse block

__device__ unsigned short g_tmp[NT];   // pass-1 distances (0xFFFF = empty row)
__device__ unsigned       g_max;       // max d2 (float bits, nonneg)
__device__ unsigned       g_cnt;       // barrier counter

// ---------------------------------------------------------------------------
// k_row: 256 blocks x 256 thr; warp handles one row.
__global__ __launch_bounds__(256) void k_row(const float* __restrict__ mask) {
    const int lane = threadIdx.x & 31;
    const int warp = threadIdx.x >> 5;
    const int row  = blockIdx.x * 8 + warp;        // b*H + y

    if (blockIdx.x == 0 && threadIdx.x == 0) { g_cnt = 0u; g_max = 0u; }

    // Load whole row: 2 x float4 per lane
    const float4* row4 = reinterpret_cast<const float4*>(mask + row * W_);
    const float4 a = row4[lane];
    const float4 bq = row4[lane + 32];

    // nibble -> 32-bit words via shfl-or; lanes 8g..8g+7 hold word g
    unsigned va = ((a.x > THR ? 1u : 0u) | (a.y > THR ? 2u : 0u)
                 | (a.z > THR ? 4u : 0u) | (a.w > THR ? 8u : 0u)) << ((lane & 7) * 4);
    unsigned vb = ((bq.x > THR ? 1u : 0u) | (bq.y > THR ? 2u : 0u)
                 | (bq.z > THR ? 4u : 0u) | (bq.w > THR ? 8u : 0u)) << ((lane & 7) * 4);
    va |= __shfl_xor_sync(0xffffffffu, va, 1);
    vb |= __shfl_xor_sync(0xffffffffu, vb, 1);
    va |= __shfl_xor_sync(0xffffffffu, va, 2);
    vb |= __shfl_xor_sync(0xffffffffu, vb, 2);
    va |= __shfl_xor_sync(0xffffffffu, va, 4);
    vb |= __shfl_xor_sync(0xffffffffu, vb, 4);

    unsigned w[8];
    #pragma unroll
    for (int j = 0; j < 4; ++j) {
        w[j]     = __shfl_sync(0xffffffffu, va, j * 8);
        w[4 + j] = __shfl_sync(0xffffffffu, vb, j * 8);
    }

    unsigned short* trow = g_tmp + row * W_;
    const unsigned mLo = 0xFFFFFFFFu >> (31 - lane);
    const unsigned mHi = 0xFFFFFFFFu << lane;

    #pragma unroll
    for (int j = 0; j < 8; ++j) {                  // pixel x = 32*j + lane
        int dl = BIG, dr = BIG;
        unsigned m = w[j] & mLo;
        if (m) dl = lane - (31 - __clz(m));
        #pragma unroll
        for (int wi = j - 1; wi >= 0; --wi)
            if (dl == BIG) {
                const unsigned ww = w[wi];
                if (ww) dl = (j - wi) * 32 + lane - (31 - __clz(ww));
            }
        m = w[j] & mHi;
        if (m) dr = (__ffs(m) - 1) - lane;
        #pragma unroll
        for (int wi = j + 1; wi < 8; ++wi)
            if (dr == BIG) {
                const unsigned ww = w[wi];
                if (ww) dr = (wi - j) * 32 + (__ffs(ww) - 1) - lane;
            }
        const int d = min(dl, dr);
        trow[j * 32 + lane] = (d <= 255) ? (unsigned short)d : (unsigned short)0xFFFF;
    }
}

// ---------------------------------------------------------------------------
// k_fuse: 64 blocks x 1024 thr. Block = (image b, 32-column tile x0).
__global__ __launch_bounds__(1024) void k_fuse(float* __restrict__ out) {
    const int blk = blockIdx.x;
    const int b   = blk >> 3;                      // image
    const int x0  = (blk & 7) * CPB2;              // column tile base
    const int t   = threadIdx.x;

    __shared__ float tmp2[H_ * CPB2];              // pre-squared pass-1 values, 32KB
    __shared__ float red[32];
    __shared__ float s_scale;

    // Load 16KB of u16: thread t -> row r = t>>2, quarter q = t&3 (8 u16 = 16B each)
    {
        const int r = t >> 2;
        const int q = t & 3;
        const uint4 v = *reinterpret_cast<const uint4*>(
            g_tmp + (b * H_ + r) * W_ + x0 + q * 8);
        const unsigned short* u = reinterpret_cast<const unsigned short*>(&v);
        #pragma unroll
        for (int cc = 0; cc < 8; ++cc) {
            const unsigned d = u[cc];
            tmp2[r * CPB2 + q * 8 + cc] = (d == 0xFFFFu) ? INF_F : (float)(d * d);
        }
    }
    __syncthreads();

    const int c  = t & 31;                         // column (== lane; bank == c)
    const int yb = t >> 5;                         // 0..31
    float bestv[8];
    float lmax = 0.0f;

    #pragma unroll
    for (int i = 0; i < 8; ++i) {
        const int y = yb + i * 32;
        float best = tmp2[y * CPB2 + c];
        #pragma unroll 1
        for (int k = 1; k < H_; ++k) {
            const float kk = (float)(k * k);
            if (kk >= best) break;                 // exact prune (tmp2 >= 0)
            const int ym = y - k;
            if (ym >= 0) best = fminf(best, kk + tmp2[ym * CPB2 + c]);
            const int yp = y + k;
            if (yp < H_) best = fminf(best, kk + tmp2[yp * CPB2 + c]);
        }
        bestv[i] = best;
        lmax = fmaxf(lmax, best);
    }

    // block max -> global atomic -> 64-arrival grid barrier (busy poll, no sleep)
    #pragma unroll
    for (int off = 16; off; off >>= 1)
        lmax = fmaxf(lmax, __shfl_xor_sync(0xffffffffu, lmax, off));
    if ((t & 31) == 0) red[t >> 5] = lmax;
    __syncthreads();
    if (t == 0) {
        float bm = red[0];
        #pragma unroll
        for (int i = 1; i < 32; ++i) bm = fmaxf(bm, red[i]);
        atomicMax(&g_max, __float_as_uint(bm));
        __threadfence();
        atomicAdd(&g_cnt, 1u);
        while (__ldcg(&g_cnt) < (unsigned)NBLK2) { }
        __threadfence();
        s_scale = 50.0f / (sqrtf(__uint_as_float(__ldcg(&g_max))) + 1.0f);
    }
    __syncthreads();
    const float s = s_scale;

    // fused epilogue straight from registers; warp = 32 consecutive columns
    float* obase = out + b * H_ * W_ + x0;
    #pragma unroll
    for (int i = 0; i < 8; ++i) {
        const int y = yb + i * 32;
        obase[y * W_ + c] = 2.0f / (1.0f + __expf(sqrtf(bestv[i]) * s));
    }
}

// ---------------------------------------------------------------------------
extern "C" void kernel_launch(void* const* d_in, const int* in_sizes, int n_in,
                              void* d_out, int out_size) {
    const float* mask = (const float*)d_in[0];
    float* out = (float*)d_out;
    k_row<<<B_ * H_ / 8, 256>>>(mask);
    k_fuse<<<NBLK2, 1024>>>(out);
}

// round 11
// speedup vs baseline: 1.0519x; 1.0519x over previous
#include <cuda_runtime.h>
#include <math.h>

// mask [8,256,256] fp32 -> EDT (separable squared) -> normalize by global max -> sigmoid.
// 2-kernel pipeline:
//   k_row : warp-per-row; 2x LDG.128 + nibble-shfl bitmap; nearest-set-bit;
//           stores PRE-SQUARED float distances -> g_tmp (L2-resident).
//           Also resets barrier counter + global max (stream-ordered => graph-safe).
//   k_fuse: 64 blocks x 1024 thr (32 cols/block). Joint-k pruned column min-plus
//           (8 outputs/thread in registers, one divergent branch per k), per-block
//           atomicMax, single 64-arrival spin barrier, fused sigmoid epilogue.
constexpr int B_ = 8;
constexpr int H_ = 256;
constexpr int W_ = 256;
constexpr int NT = B_ * H_ * W_;
constexpr float THR   = 0.5f;
constexpr float INF_F = 1e10f;
constexpr int BIG = 1 << 29;
constexpr int NBLK2 = 64;          // 8 images * 8 column-tiles
constexpr int CPB2  = 32;          // columns per k_fuse block

__device__ float    g_tmp[NT];     // pass-1 squared distances (1e10 = empty row)
__device__ unsigned g_max;         // max d2 (float bits, nonneg)
__device__ unsigned g_cnt;         // barrier counter

// ---------------------------------------------------------------------------
// k_row: 256 blocks x 256 thr; warp handles one row.
__global__ __launch_bounds__(256) void k_row(const float* __restrict__ mask) {
    const int lane = threadIdx.x & 31;
    const int warp = threadIdx.x >> 5;
    const int row  = blockIdx.x * 8 + warp;        // b*H + y

    if (blockIdx.x == 0 && threadIdx.x == 0) { g_cnt = 0u; g_max = 0u; }

    // Load whole row: 2 x float4 per lane
    const float4* row4 = reinterpret_cast<const float4*>(mask + row * W_);
    const float4 a = row4[lane];
    const float4 bq = row4[lane + 32];

    // nibble -> 32-bit words via shfl-or; lanes 8g..8g+7 hold word g
    unsigned va = ((a.x > THR ? 1u : 0u) | (a.y > THR ? 2u : 0u)
                 | (a.z > THR ? 4u : 0u) | (a.w > THR ? 8u : 0u)) << ((lane & 7) * 4);
    unsigned vb = ((bq.x > THR ? 1u : 0u) | (bq.y > THR ? 2u : 0u)
                 | (bq.z > THR ? 4u : 0u) | (bq.w > THR ? 8u : 0u)) << ((lane & 7) * 4);
    va |= __shfl_xor_sync(0xffffffffu, va, 1);
    vb |= __shfl_xor_sync(0xffffffffu, vb, 1);
    va |= __shfl_xor_sync(0xffffffffu, va, 2);
    vb |= __shfl_xor_sync(0xffffffffu, vb, 2);
    va |= __shfl_xor_sync(0xffffffffu, va, 4);
    vb |= __shfl_xor_sync(0xffffffffu, vb, 4);

    unsigned w[8];
    #pragma unroll
    for (int j = 0; j < 4; ++j) {
        w[j]     = __shfl_sync(0xffffffffu, va, j * 8);
        w[4 + j] = __shfl_sync(0xffffffffu, vb, j * 8);
    }

    float* trow = g_tmp + row * W_;
    const unsigned mLo = 0xFFFFFFFFu >> (31 - lane);
    const unsigned mHi = 0xFFFFFFFFu << lane;

    #pragma unroll
    for (int j = 0; j < 8; ++j) {                  // pixel x = 32*j + lane
        int dl = BIG, dr = BIG;
        unsigned m = w[j] & mLo;
        if (m) dl = lane - (31 - __clz(m));
        #pragma unroll
        for (int wi = j - 1; wi >= 0; --wi)
            if (dl == BIG) {
                const unsigned ww = w[wi];
                if (ww) dl = (j - wi) * 32 + lane - (31 - __clz(ww));
            }
        m = w[j] & mHi;
        if (m) dr = (__ffs(m) - 1) - lane;
        #pragma unroll
        for (int wi = j + 1; wi < 8; ++wi)
            if (dr == BIG) {
                const unsigned ww = w[wi];
                if (ww) dr = (wi - j) * 32 + (__ffs(ww) - 1) - lane;
            }
        const int d = min(dl, dr);
        trow[j * 32 + lane] = (d <= 255) ? (float)(d * d) : INF_F;  // pre-squared
    }
}

// ---------------------------------------------------------------------------
// k_fuse: 64 blocks x 1024 thr. Block = (image b, 32-column tile x0).
__global__ __launch_bounds__(1024) void k_fuse(float* __restrict__ out) {
    const int blk = blockIdx.x;
    const int b   = blk >> 3;                      // image
    const int x0  = (blk & 7) * CPB2;              // column tile base
    const int t   = threadIdx.x;

    __shared__ float tmp2[H_ * CPB2];              // squared pass-1 values, 32KB
    __shared__ float red[32];
    __shared__ float s_scale;

    const int c  = t & 31;                         // column (== lane; bank == c)
    const int g5 = t >> 5;                         // warp id 0..31

    // Load: lane = column (conflict-free STS, coalesced LDG, MLP=8)
    {
        const int r0 = g5 * 8;
        const float* src = g_tmp + (b * H_ + r0) * W_ + x0 + c;
        #pragma unroll
        for (int i = 0; i < 8; ++i)
            tmp2[(r0 + i) * CPB2 + c] = src[i * W_];
    }
    __syncthreads();

    // Pass 2, joint-k: best[i] over y in {g5, g5+32, ..., g5+224}
    const int yb = g5;
    float best[8];
    float bmax = 0.0f;
    #pragma unroll
    for (int i = 0; i < 8; ++i) {
        best[i] = tmp2[(yb + i * 32) * CPB2 + c];
        bmax = fmaxf(bmax, best[i]);
    }

    #pragma unroll 1
    for (int k = 1; k < H_; ++k) {
        const float kk = (float)(k * k);
        if (kk >= bmax) break;                     // exact prune (tmp2 >= 0)
        bmax = 0.0f;
        #pragma unroll
        for (int i = 0; i < 8; ++i) {
            const int y = yb + i * 32;
            const int ym = y - k;
            if (ym >= 0)  best[i] = fminf(best[i], kk + tmp2[ym * CPB2 + c]);
            const int yp = y + k;
            if (yp < H_)  best[i] = fminf(best[i], kk + tmp2[yp * CPB2 + c]);
            bmax = fmaxf(bmax, best[i]);
        }
    }
    // bmax == per-lane final max (loop exit implies no further improvement)

    // block max -> global atomic -> 64-arrival grid barrier (busy poll)
    float lmax = bmax;
    #pragma unroll
    for (int off = 16; off; off >>= 1)
        lmax = fmaxf(lmax, __shfl_xor_sync(0xffffffffu, lmax, off));
    if (c == 0) red[g5] = lmax;
    __syncthreads();
    if (t == 0) {
        float bm = red[0];
        #pragma unroll
        for (int i = 1; i < 32; ++i) bm = fmaxf(bm, red[i]);
        atomicMax(&g_max, __float_as_uint(bm));
        __threadfence();
        atomicAdd(&g_cnt, 1u);
        while (__ldcg(&g_cnt) < (unsigned)NBLK2) { }
        __threadfence();
        s_scale = 50.0f / (sqrtf(__uint_as_float(__ldcg(&g_max))) + 1.0f);
    }
    __syncthreads();
    const float s = s_scale;

    // fused epilogue straight from registers; warp = 32 consecutive columns
    float* obase = out + b * H_ * W_ + x0;
    #pragma unroll
    for (int i = 0; i < 8; ++i) {
        const int y = yb + i * 32;
        obase[y * W_ + c] = __fdividef(2.0f, 1.0f + __expf(sqrtf(best[i]) * s));
    }
}

// ---------------------------------------------------------------------------
extern "C" void kernel_launch(void* const* d_in, const int* in_sizes, int n_in,
                              void* d_out, int out_size) {
    const float* mask = (const float*)d_in[0];
    float* out = (float*)d_out;
    k_row<<<B_ * H_ / 8, 256>>>(mask);
    k_fuse<<<NBLK2, 1024>>>(out);
}

// round 12
// speedup vs baseline: 1.0858x; 1.0322x over previous
#include <cuda_runtime.h>
#include <math.h>

// mask [8,256,256] fp32 -> EDT (separable squared) -> normalize by global max -> sigmoid.
// 2-kernel pipeline:
//   k_row : warp-per-row; 2x LDG.128 + nibble-shfl bitmap; nearest-set-bit;
//           stores PRE-SQUARED float distances -> g_tmp (L2-resident).
//           Also resets barrier counter + global max (stream-ordered => graph-safe).
//   k_fuse: 128 blocks x 512 thr (16 cols/block; 1 block/SM, single wave).
//           Joint-k pruned column min-plus (8 outputs/thread in registers),
//           per-block atomicMax, single 128-arrival spin barrier, fused sigmoid.
constexpr int B_ = 8;
constexpr int H_ = 256;
constexpr int W_ = 256;
constexpr int NT = B_ * H_ * W_;
constexpr float THR   = 0.5f;
constexpr float INF_F = 1e10f;
constexpr int BIG = 1 << 29;
constexpr int NBLK2 = 128;         // 8 images * 16 column-tiles
constexpr int CPB2  = 16;          // columns per k_fuse block

__device__ float    g_tmp[NT];     // pass-1 squared distances (1e10 = empty row)
__device__ unsigned g_max;         // max d2 (float bits, nonneg)
__device__ unsigned g_cnt;         // barrier counter

// ---------------------------------------------------------------------------
// k_row: 256 blocks x 256 thr; warp handles one row.
__global__ __launch_bounds__(256) void k_row(const float* __restrict__ mask) {
    const int lane = threadIdx.x & 31;
    const int warp = threadIdx.x >> 5;
    const int row  = blockIdx.x * 8 + warp;        // b*H + y

    if (blockIdx.x == 0 && threadIdx.x == 0) { g_cnt = 0u; g_max = 0u; }

    // Load whole row: 2 x float4 per lane
    const float4* row4 = reinterpret_cast<const float4*>(mask + row * W_);
    const float4 a = row4[lane];
    const float4 bq = row4[lane + 32];

    // nibble -> 32-bit words via shfl-or; lanes 8g..8g+7 hold word g
    unsigned va = ((a.x > THR ? 1u : 0u) | (a.y > THR ? 2u : 0u)
                 | (a.z > THR ? 4u : 0u) | (a.w > THR ? 8u : 0u)) << ((lane & 7) * 4);
    unsigned vb = ((bq.x > THR ? 1u : 0u) | (bq.y > THR ? 2u : 0u)
                 | (bq.z > THR ? 4u : 0u) | (bq.w > THR ? 8u : 0u)) << ((lane & 7) * 4);
    va |= __shfl_xor_sync(0xffffffffu, va, 1);
    vb |= __shfl_xor_sync(0xffffffffu, vb, 1);
    va |= __shfl_xor_sync(0xffffffffu, va, 2);
    vb |= __shfl_xor_sync(0xffffffffu, vb, 2);
    va |= __shfl_xor_sync(0xffffffffu, va, 4);
    vb |= __shfl_xor_sync(0xffffffffu, vb, 4);

    unsigned w[8];
    #pragma unroll
    for (int j = 0; j < 4; ++j) {
        w[j]     = __shfl_sync(0xffffffffu, va, j * 8);
        w[4 + j] = __shfl_sync(0xffffffffu, vb, j * 8);
    }

    float* trow = g_tmp + row * W_;
    const unsigned mLo = 0xFFFFFFFFu >> (31 - lane);
    const unsigned mHi = 0xFFFFFFFFu << lane;

    #pragma unroll
    for (int j = 0; j < 8; ++j) {                  // pixel x = 32*j + lane
        int dl = BIG, dr = BIG;
        unsigned m = w[j] & mLo;
        if (m) dl = lane - (31 - __clz(m));
        #pragma unroll
        for (int wi = j - 1; wi >= 0; --wi)
            if (dl == BIG) {
                const unsigned ww = w[wi];
                if (ww) dl = (j - wi) * 32 + lane - (31 - __clz(ww));
            }
        m = w[j] & mHi;
        if (m) dr = (__ffs(m) - 1) - lane;
        #pragma unroll
        for (int wi = j + 1; wi < 8; ++wi)
            if (dr == BIG) {
                const unsigned ww = w[wi];
                if (ww) dr = (wi - j) * 32 + (__ffs(ww) - 1) - lane;
            }
        const int d = min(dl, dr);
        trow[j * 32 + lane] = (d <= 255) ? (float)(d * d) : INF_F;  // pre-squared
    }
}

// ---------------------------------------------------------------------------
// k_fuse: 128 blocks x 512 thr. Block = (image b, 16-column tile x0).
__global__ __launch_bounds__(512) void k_fuse(float* __restrict__ out) {
    const int blk = blockIdx.x;
    const int b   = blk >> 4;                      // image
    const int x0  = (blk & 15) * CPB2;             // column tile base
    const int t   = threadIdx.x;

    __shared__ float tmp2[H_ * CPB2];              // squared pass-1 values, 16KB
    __shared__ float red[16];
    __shared__ float s_scale;

    const int c  = t & 15;                         // column within tile
    const int yb = t >> 4;                         // 0..31

    // Load: thread's own 8 rows (y = yb + i*32) -> registers AND smem.
    // Warp = 2 rows x 16 cols: 2x64B LDG segments; smem banks 32-distinct.
    float best[8];
    float bmax = 0.0f;
    {
        const float* src = g_tmp + b * H_ * W_ + x0 + c;
        #pragma unroll
        for (int i = 0; i < 8; ++i) {
            const int y = yb + i * 32;
            const float v = src[y * W_];
            best[i] = v;
            tmp2[y * CPB2 + c] = v;
            bmax = fmaxf(bmax, v);
        }
    }
    __syncthreads();

    // Pass 2, joint-k pruned: one divergent branch per k, 8 fmin chains (ILP)
    #pragma unroll 1
    for (int k = 1; k < H_; ++k) {
        const float kk = (float)(k * k);
        if (kk >= bmax) break;                     // exact prune (tmp2 >= 0)
        bmax = 0.0f;
        #pragma unroll
        for (int i = 0; i < 8; ++i) {
            const int y = yb + i * 32;
            const int ym = y - k;
            if (ym >= 0)  best[i] = fminf(best[i], kk + tmp2[ym * CPB2 + c]);
            const int yp = y + k;
            if (yp < H_)  best[i] = fminf(best[i], kk + tmp2[yp * CPB2 + c]);
            bmax = fmaxf(bmax, best[i]);
        }
    }

    // block max -> global atomic -> 128-arrival grid barrier (busy poll)
    float lmax = bmax;
    #pragma unroll
    for (int off = 16; off; off >>= 1)
        lmax = fmaxf(lmax, __shfl_xor_sync(0xffffffffu, lmax, off));
    if ((t & 31) == 0) red[t >> 5] = lmax;
    __syncthreads();
    if (t == 0) {
        float bm = red[0];
        #pragma unroll
        for (int i = 1; i < 16; ++i) bm = fmaxf(bm, red[i]);
        atomicMax(&g_max, __float_as_uint(bm));
        __threadfence();
        atomicAdd(&g_cnt, 1u);
        while (__ldcg(&g_cnt) < (unsigned)NBLK2) { }
        __threadfence();
        s_scale = 50.0f / (sqrtf(__uint_as_float(__ldcg(&g_max))) + 1.0f);
    }
    __syncthreads();
    const float s = s_scale;

    // fused epilogue straight from registers; warp = 2 rows x 16 cols (2x64B)
    float* obase = out + b * H_ * W_ + x0 + c;
    #pragma unroll
    for (int i = 0; i < 8; ++i) {
        const int y = yb + i * 32;
        obase[y * W_] = __fdividef(2.0f, 1.0f + __expf(sqrtf(best[i]) * s));
    }
}

// ---------------------------------------------------------------------------
extern "C" void kernel_launch(void* const* d_in, const int* in_sizes, int n_in,
                              void* d_out, int out_size) {
    const float* mask = (const float*)d_in[0];
    float* out = (float*)d_out;
    k_row<<<B_ * H_ / 8, 256>>>(mask);
    k_fuse<<<NBLK2, 512>>>(out);
}